// round 14
// baseline (speedup 1.0000x reference)
#include <cuda_runtime.h>

// ---------------------------------------------------------------------------
// VQ-VAE forward.  Encoder in double-float (df48) on the fp32 pipe (f32x2) --
// z must round to the exact value (any argmin flip fails).  VQ emulates the
// reference's fp32 distance rounding.  Decoder fp32 packed (NCHW g2).
// R11 configuration; VQ embed staging coalesced.
// ---------------------------------------------------------------------------

#define BATCH 32
typedef unsigned long long u64;

__device__ float2 g_h1[BATCH * 64 * 128 * 128];   // e1 out NCHW, df(hi,lo)
__device__ float2 g_h2[BATCH * 128 * 64 * 64];    // e2 out NCHW, df(hi,lo)
__device__ float  g_z32[BATCH * 64 * 64 * 32];    // e3 out BHWC, fp32
__device__ float  g_zq[BATCH * 64 * 64 * 32];     // straight-through z_q_st
__device__ float  g_g1[BATCH * 128 * 64 * 64];    // d1 out NCHW
__device__ float  g_g2[BATCH * 64 * 128 * 128];   // d2 out NCHW
__device__ double g_lp[1024];                     // loss partials

// transposed weights, [ic][tap][oc] (oc contiguous -> adjacent pairs = u64)
__device__ __align__(16) float g_we2t[64 * 16 * 128];
__device__ __align__(16) float g_we3t[128 * 9 * 32];
__device__ __align__(16) float g_wd1t[32 * 9 * 128];   // tap pre-flipped
__device__ __align__(16) float g_wd2t[128 * 16 * 64];

// ---- packed f32x2 helpers --------------------------------------------------
__device__ __forceinline__ u64 pk(float a, float b) {
    u64 r; asm("mov.b64 %0,{%1,%2};" : "=l"(r) : "f"(a), "f"(b)); return r;
}
__device__ __forceinline__ void upk(u64 v, float& a, float& b) {
    asm("mov.b64 {%0,%1},%2;" : "=f"(a), "=f"(b) : "l"(v));
}
__device__ __forceinline__ u64 f2mul(u64 a, u64 b) {
    u64 d; asm("mul.rn.f32x2 %0,%1,%2;" : "=l"(d) : "l"(a), "l"(b)); return d;
}
__device__ __forceinline__ u64 f2add(u64 a, u64 b) {
    u64 d; asm("add.rn.f32x2 %0,%1,%2;" : "=l"(d) : "l"(a), "l"(b)); return d;
}
__device__ __forceinline__ u64 f2fma(u64 a, u64 b, u64 c) {
    u64 d; asm("fma.rn.f32x2 %0,%1,%2,%3;" : "=l"(d) : "l"(a), "l"(b), "l"(c)); return d;
}

// ---- cp.async helpers ------------------------------------------------------
__device__ __forceinline__ unsigned smem_u32(const void* p) {
    unsigned a;
    asm("{ .reg .u64 t; cvta.to.shared.u64 t, %1; cvt.u32.u64 %0, t; }"
        : "=r"(a) : "l"(p));
    return a;
}
__device__ __forceinline__ void cp_async8(unsigned dst, const void* src, bool ok) {
    int sz = ok ? 8 : 0;
    asm volatile("cp.async.ca.shared.global [%0], [%1], 8, %2;"
                 :: "r"(dst), "l"(src), "r"(sz));
}
__device__ __forceinline__ void cp_commit() {
    asm volatile("cp.async.commit_group;");
}
template<int N> __device__ __forceinline__ void cp_wait() {
    asm volatile("cp.async.wait_group %0;" :: "n"(N));
}

// df MAC, fp32 scalar input (exact), packed weight pair: 7 packed ops
#define DFMAC_F(hi, lo, vd, vdn, w2)                               \
    {   u64 _p  = f2mul(vd, w2);                                   \
        u64 _nc = f2fma(vdn, w2, _p);                              \
        u64 _s  = f2add(hi, _p);                                   \
        u64 _t  = f2fma(hi, NEG1, _s);                             \
        u64 _nr = f2fma(_p, NEG1, _t);                             \
        u64 _nd = f2add(_nr, _nc);                                 \
        lo = f2fma(_nd, NEG1, lo);                                 \
        hi = _s; }

// df MAC, df input: 8 packed ops
#define DFMAC_DF(hi, lo, vd, vdn, vln, w2)                         \
    {   u64 _p  = f2mul(vd, w2);                                   \
        u64 _nc = f2fma(vdn, w2, _p);                              \
        _nc = f2fma(vln, w2, _nc);                                 \
        u64 _s  = f2add(hi, _p);                                   \
        u64 _t  = f2fma(hi, NEG1, _s);                             \
        u64 _nr = f2fma(_p, NEG1, _t);                             \
        u64 _nd = f2add(_nr, _nc);                                 \
        lo = f2fma(_nd, NEG1, lo);                                 \
        hi = _s; }

__device__ __forceinline__ float2 df_relu_out(u64 hiP, u64 loP, bool high,
                                              float bias) {
    float ah, bh, al, bl;
    upk(hiP, ah, bh); upk(loP, al, bl);
    double dv = high ? ((double)bh + (double)bl + (double)bias)
                     : ((double)ah + (double)al + (double)bias);
    float2 o;
    if (dv > 0.0) { o.x = (float)dv; o.y = (float)(dv - (double)o.x); }
    else          { o.x = 0.f; o.y = 0.f; }
    return o;
}

// ---------------------------------------------------------------------------
// prep: transpose weights into [ic][tap][oc] device buffers.
// ---------------------------------------------------------------------------
__global__ void prep_weights(const float* __restrict__ e_w2,
                             const float* __restrict__ e_w3,
                             const float* __restrict__ d_w1,
                             const float* __restrict__ d_w2) {
    int i = blockIdx.x * 256 + threadIdx.x;
    if (i < 131072) {            // e2: [64ic][16t][128oc]
        int oc = i & 127, t = (i >> 7) & 15, ic = i >> 11;
        g_we2t[i] = e_w2[(oc * 64 + ic) * 16 + t];
    }
    if (i < 36864) {             // e3: [128ic][9t][32oc]
        int oc = i & 31, j = i >> 5, t = j % 9, ic = j / 9;
        g_we3t[i] = e_w3[(oc * 128 + ic) * 9 + t];
    }
    if (i < 36864) {             // d1: [32ic][9t][128oc], tap flipped
        int oc = i & 127, j = i >> 7, t = j % 9, ic = j / 9;
        g_wd1t[i] = d_w1[(ic * 128 + oc) * 9 + (8 - t)];
    }
    if (i < 131072) {            // d2: [128ic][16t][64oc]
        int oc = i & 63, j = i >> 6, t = j & 15, ic = j >> 4;
        g_wd2t[i] = d_w2[(ic * 64 + oc) * 16 + t];
    }
}

// ---------------------------------------------------------------------------
// e1: conv 3->64, k4 s2 p1, 256->128, relu.  df out.  smem-staged input.
// ---------------------------------------------------------------------------
__global__ void e1_kernel(const float* __restrict__ x, const float* __restrict__ w,
                          const float* __restrict__ bias) {
    __shared__ __align__(8) float w_s[48 * 32];
    __shared__ float in_s[3][4][260];                 // [ic][ky][ix+1]
    const int oy = blockIdx.x, half = blockIdx.y, b = blockIdx.z;
    const int ox = threadIdx.x;
    for (int i = threadIdx.x; i < 1536; i += 128) {
        int t = i >> 5, j = i & 31;
        w_s[t * 32 + j] = w[(half * 32 + j) * 48 + t];
    }
    for (int idx = threadIdx.x; idx < 3096; idx += 128) {
        int ic = idx / 1032, r = idx % 1032;
        int ky = r / 258, ixm = r % 258;
        int iy = 2 * oy - 1 + ky, gx = ixm - 1;
        float v = 0.f;
        if ((unsigned)iy < 256u && (unsigned)gx < 256u)
            v = x[((b * 3 + ic) * 256 + iy) * 256 + gx];
        in_s[ic][ky][ixm] = v;
    }
    __syncthreads();
    const u64* w64 = reinterpret_cast<const u64*>(w_s);
    const u64 NEG1 = pk(-1.f, -1.f);

    u64 ahi[16], alo[16];
#pragma unroll
    for (int q = 0; q < 16; q++) { ahi[q] = 0ull; alo[q] = 0ull; }

#pragma unroll
    for (int ic = 0; ic < 3; ic++) {
#pragma unroll
        for (int ky = 0; ky < 4; ky++) {
#pragma unroll
            for (int kx = 0; kx < 4; kx++) {
                float v = in_s[ic][ky][2 * ox + kx];
                u64 vd = pk(v, v), vdn = pk(-v, -v);
                const u64* wp = w64 + (ic * 16 + ky * 4 + kx) * 16;
#pragma unroll
                for (int q = 0; q < 16; q++)
                    DFMAC_F(ahi[q], alo[q], vd, vdn, wp[q]);
            }
        }
    }
#pragma unroll
    for (int q = 0; q < 16; q++) {
        int oc = half * 32 + 2 * q;
        g_h1[((b * 64 + oc) * 128 + oy) * 128 + ox] =
            df_relu_out(ahi[q], alo[q], false, bias[oc]);
        g_h1[((b * 64 + oc + 1) * 128 + oy) * 128 + ox] =
            df_relu_out(ahi[q], alo[q], true, bias[oc + 1]);
    }
}

// ---------------------------------------------------------------------------
// e2: conv 64->128, k4 s2 p1, 128->64, relu.  df.  2 pixels/thread.
// R11 winner: 256 threads, ocT in {0,1}, 4-ic double-buffered cp.async.
// ---------------------------------------------------------------------------
__global__ void __launch_bounds__(256, 2)
e2_kernel(const float* __restrict__ bias) {
    __shared__ float2 in_s[2][4 * 18 * 34];
    const int s = blockIdx.x, ocT = blockIdx.y, b = blockIdx.z;
    const int tid = threadIdx.x;
    const int pos = tid & 63, grp = tid >> 6;
    const int py = pos >> 3, px = pos & 7;
    const int ty0 = (s >> 2) * 8, tx0 = (s & 3) * 16;
    const int iyb = 2 * ty0 - 1, ixb = 2 * tx0 - 1;
    const int ocbase = ocT * 64 + grp * 16;
    const u64 NEG1 = pk(-1.f, -1.f);
    const unsigned sb0 = smem_u32(&in_s[0][0]);

    u64 a0[8], l0[8], a1[8], l1[8];
#pragma unroll
    for (int q = 0; q < 8; q++) { a0[q] = 0ull; l0[q] = 0ull; a1[q] = 0ull; l1[q] = 0ull; }

    auto load_stage = [&](int icc, int buf) {
        unsigned base = sb0 + (unsigned)buf * 2448u * 8u;
        for (int idx = tid; idx < 2448; idx += 256) {
            int ic = idx / 612, r = idx % 612;
            int iy = r / 34, ix = r % 34;
            int gy = iyb + iy, gx = ixb + ix;
            bool ok = ((unsigned)gy < 128u && (unsigned)gx < 128u);
            const float2* src = &g_h1[((b * 64 + icc * 4 + ic) * 128 +
                                       (ok ? gy : 0)) * 128 + (ok ? gx : 0)];
            cp_async8(base + (unsigned)idx * 8u, src, ok);
        }
        cp_commit();
    };

    load_stage(0, 0);

    for (int icc = 0; icc < 16; icc++) {
        if (icc < 15) { load_stage(icc + 1, (icc + 1) & 1); cp_wait<1>(); }
        else          { cp_wait<0>(); }
        __syncthreads();

        const float2* cur = in_s[icc & 1];
#pragma unroll
        for (int ic = 0; ic < 4; ic++) {
#pragma unroll
            for (int ky = 0; ky < 4; ky++) {
                const float2* row = cur + ic * 612 + (2 * py + ky) * 34 + 2 * px;
#pragma unroll
                for (int kx = 0; kx < 4; kx++) {
                    float2 v0 = row[kx];
                    float2 v1 = row[kx + 16];
                    const ulonglong2* wp = reinterpret_cast<const ulonglong2*>(
                        g_we2t + ((icc * 4 + ic) * 16 + ky * 4 + kx) * 128 + ocbase);
                    ulonglong2 wq0 = wp[0], wq1 = wp[1], wq2 = wp[2], wq3 = wp[3];
                    u64 w2[8];
                    w2[0] = wq0.x; w2[1] = wq0.y;
                    w2[2] = wq1.x; w2[3] = wq1.y;
                    w2[4] = wq2.x; w2[5] = wq2.y;
                    w2[6] = wq3.x; w2[7] = wq3.y;
                    u64 vd0 = pk(v0.x, v0.x), vdn0 = pk(-v0.x, -v0.x), vln0 = pk(-v0.y, -v0.y);
                    u64 vd1 = pk(v1.x, v1.x), vdn1 = pk(-v1.x, -v1.x), vln1 = pk(-v1.y, -v1.y);
#pragma unroll
                    for (int q = 0; q < 8; q++) {
                        DFMAC_DF(a0[q], l0[q], vd0, vdn0, vln0, w2[q]);
                        DFMAC_DF(a1[q], l1[q], vd1, vdn1, vln1, w2[q]);
                    }
                }
            }
        }
        __syncthreads();
    }

    const int oy = ty0 + py, ox0 = tx0 + px, ox1 = tx0 + px + 8;
#pragma unroll
    for (int q = 0; q < 8; q++) {
        int oc = ocbase + 2 * q;
        long b0 = ((long)(b * 128 + oc) * 64 + oy) * 64;
        long b1 = ((long)(b * 128 + oc + 1) * 64 + oy) * 64;
        g_h2[b0 + ox0] = df_relu_out(a0[q], l0[q], false, bias[oc]);
        g_h2[b1 + ox0] = df_relu_out(a0[q], l0[q], true,  bias[oc + 1]);
        g_h2[b0 + ox1] = df_relu_out(a1[q], l1[q], false, bias[oc]);
        g_h2[b1 + ox1] = df_relu_out(a1[q], l1[q], true,  bias[oc + 1]);
    }
}

// ---------------------------------------------------------------------------
// e3: conv 128->32, k3 s1 p1, 64->64, relu.  df in, fp32 out BHWC.  (R11)
// ---------------------------------------------------------------------------
__global__ void e3_kernel(const float* __restrict__ bias) {
    __shared__ float2 in_s[2][8 * 100];
    const int s = blockIdx.x, b = blockIdx.z;
    const int tid = threadIdx.x;
    const int pos = tid & 63, grp = tid >> 6;
    const int py = pos >> 3, px = pos & 7;
    const int ty0 = (s >> 3) * 8, tx0 = (s & 7) * 8;
    const u64 NEG1 = pk(-1.f, -1.f);
    const unsigned sb0 = smem_u32(&in_s[0][0]);

    u64 ahi[4], alo[4];
#pragma unroll
    for (int q = 0; q < 4; q++) { ahi[q] = 0ull; alo[q] = 0ull; }

    auto load_stage = [&](int icc, int buf) {
        unsigned base = sb0 + (unsigned)buf * 800u * 8u;
        for (int idx = tid; idx < 800; idx += 256) {
            int ic = idx / 100, r = idx % 100;
            int iy = r / 10, ix = r % 10;
            int gy = ty0 - 1 + iy, gx = tx0 - 1 + ix;
            bool ok = ((unsigned)gy < 64u && (unsigned)gx < 64u);
            const float2* src = &g_h2[((b * 128 + icc * 8 + ic) * 64 +
                                       (ok ? gy : 0)) * 64 + (ok ? gx : 0)];
            cp_async8(base + (unsigned)idx * 8u, src, ok);
        }
        cp_commit();
    };

    load_stage(0, 0);

    for (int icc = 0; icc < 16; icc++) {
        if (icc < 15) { load_stage(icc + 1, (icc + 1) & 1); cp_wait<1>(); }
        else          { cp_wait<0>(); }
        __syncthreads();

        const float2* cur = in_s[icc & 1];
#pragma unroll
        for (int ic = 0; ic < 8; ic++) {
#pragma unroll
            for (int t = 0; t < 9; t++) {
                int ky = t / 3, kx = t % 3;
                float2 v = cur[ic * 100 + (py + ky) * 10 + px + kx];
                u64 vd  = pk(v.x, v.x);
                u64 vdn = pk(-v.x, -v.x);
                u64 vln = pk(-v.y, -v.y);
                const ulonglong2* wp = reinterpret_cast<const ulonglong2*>(
                    g_we3t + ((icc * 8 + ic) * 9 + t) * 32 + grp * 8);
                ulonglong2 wqa = wp[0], wqb = wp[1];
                DFMAC_DF(ahi[0], alo[0], vd, vdn, vln, wqa.x);
                DFMAC_DF(ahi[1], alo[1], vd, vdn, vln, wqa.y);
                DFMAC_DF(ahi[2], alo[2], vd, vdn, vln, wqb.x);
                DFMAC_DF(ahi[3], alo[3], vd, vdn, vln, wqb.y);
            }
        }
        __syncthreads();
    }

    const int oy = ty0 + py, ox = tx0 + px;
    int base = ((b * 64 + oy) * 64 + ox) * 32 + grp * 8;
#pragma unroll
    for (int q = 0; q < 4; q++) {
        float ah, bh, al, bl;
        upk(ahi[q], ah, bh); upk(alo[q], al, bl);
        double d0 = (double)ah + (double)al + (double)bias[grp * 8 + 2 * q];
        double d1 = (double)bh + (double)bl + (double)bias[grp * 8 + 2 * q + 1];
        float z0 = (float)d0, z1 = (float)d1;
        g_z32[base + 2 * q]     = z0 > 0.f ? z0 : 0.f;
        g_z32[base + 2 * q + 1] = z1 > 0.f ? z1 : 0.f;
    }
}

// ---------------------------------------------------------------------------
// VQ, reference-fp32-emulating (tie-exact).  Coalesced embed staging; B
// computed per-row from smem in the same d-order (identical values).
// ---------------------------------------------------------------------------
__global__ void vq_kernel(const float* __restrict__ embed) {
    __shared__ float s_e[128 * 33];
    __shared__ float s_B[128];
    __shared__ double s_red[128];
    const int tid = threadIdx.x;
    const long n = (long)blockIdx.x * 128 + tid;

    float zv[32];
    {
        const float4* zp = reinterpret_cast<const float4*>(g_z32 + n * 32);
#pragma unroll
        for (int d = 0; d < 8; d++) {
            float4 t = zp[d];
            zv[4 * d] = t.x; zv[4 * d + 1] = t.y;
            zv[4 * d + 2] = t.z; zv[4 * d + 3] = t.w;
        }
    }

    float A = 0.f;
#pragma unroll
    for (int d = 0; d < 32; d++)
        A = __fadd_rn(A, __fmul_rn(zv[d], zv[d]));

    float best = 3.402823466e38f;
    int bidx = 0;

    for (int c = 0; c < 4; c++) {
        __syncthreads();
        for (int idx = tid; idx < 4096; idx += 128) {
            int row = idx >> 5, d = idx & 31;
            s_e[row * 33 + d] = embed[(c << 12) + idx];   // coalesced
        }
        __syncthreads();
        {
            float Bacc = 0.f;
#pragma unroll
            for (int d = 0; d < 32; d++) {
                float e = s_e[tid * 33 + d];
                Bacc = __fadd_rn(Bacc, __fmul_rn(e, e));
            }
            s_B[tid] = Bacc;
        }
        __syncthreads();

        for (int e = 0; e < 128; e++) {
            float m = 0.f;
#pragma unroll
            for (int d = 0; d < 32; d++)
                m = __fmaf_rn(zv[d], s_e[e * 33 + d], m);
            float t1 = __fadd_rn(A, s_B[e]);
            float sc = __fsub_rn(t1, __fmul_rn(2.f, m));
            if (sc < best) { best = sc; bidx = c * 128 + e; }
        }
    }

    const float* eb = embed + bidx * 32;
    float st[32];
    double ls = 0.0;
#pragma unroll
    for (int d = 0; d < 32; d++) {
        float q = eb[d];
        float diff = __fsub_rn(q, zv[d]);
        st[d] = __fadd_rn(zv[d], diff);
        ls += (double)diff * (double)diff;
    }
    float4* qout = reinterpret_cast<float4*>(g_zq + n * 32);
#pragma unroll
    for (int q = 0; q < 8; q++)
        qout[q] = make_float4(st[4 * q], st[4 * q + 1], st[4 * q + 2], st[4 * q + 3]);

    s_red[tid] = ls;
    __syncthreads();
    for (int off = 64; off > 0; off >>= 1) {
        if (tid < off) s_red[tid] += s_red[tid + off];
        __syncthreads();
    }
    if (tid == 0) g_lp[blockIdx.x] = s_red[0];
}

__global__ void loss_reduce_kernel(float* __restrict__ out, int lossIdx) {
    __shared__ double s[256];
    int tid = threadIdx.x;
    s[tid] = g_lp[tid] + g_lp[tid + 256] + g_lp[tid + 512] + g_lp[tid + 768];
    __syncthreads();
    for (int off = 128; off > 0; off >>= 1) {
        if (tid < off) s[tid] += s[tid + off];
        __syncthreads();
    }
    if (tid == 0) out[lossIdx] = (float)(1.25 * s[0] / 4194304.0);
}

// ---------------------------------------------------------------------------
// d1: convT 32->128 k3 s1 p1.  fp32 packed; ulonglong2 weight loads.
// ---------------------------------------------------------------------------
__global__ void d1_kernel(const float* __restrict__ bias) {
    __shared__ float in_s[32 * 180];
    const int s = blockIdx.x, b = blockIdx.z;
    const int tid = threadIdx.x;
    const int pos = tid & 63, grp = tid >> 6;
    const int py = pos >> 3, px = pos & 7;
    const int ty0 = (s >> 2) * 8, tx0 = (s & 3) * 16;

    for (int i = tid; i < 1440; i += 256) {
        int pix = i >> 3, c4 = i & 7;
        int iy = pix / 18, ix = pix % 18;
        int gy = ty0 - 1 + iy, gx = tx0 - 1 + ix;
        float4 v = make_float4(0.f, 0.f, 0.f, 0.f);
        if ((unsigned)gy < 64u && (unsigned)gx < 64u)
            v = *reinterpret_cast<const float4*>(
                g_zq + ((b * 64 + gy) * 64 + gx) * 32 + c4 * 4);
        in_s[(c4 * 4 + 0) * 180 + pix] = v.x;
        in_s[(c4 * 4 + 1) * 180 + pix] = v.y;
        in_s[(c4 * 4 + 2) * 180 + pix] = v.z;
        in_s[(c4 * 4 + 3) * 180 + pix] = v.w;
    }
    __syncthreads();

    u64 a0[16], a1[16];
#pragma unroll
    for (int q = 0; q < 16; q++) { a0[q] = 0ull; a1[q] = 0ull; }

#pragma unroll 2
    for (int ic = 0; ic < 32; ic++) {
#pragma unroll
        for (int t = 0; t < 9; t++) {
            int ky = t / 3, kx = t % 3;
            float v0 = in_s[ic * 180 + (py + ky) * 18 + px + kx];
            float v1 = in_s[ic * 180 + (py + ky) * 18 + px + 8 + kx];
            u64 vp0 = pk(v0, v0), vp1 = pk(v1, v1);
            const ulonglong2* wp = reinterpret_cast<const ulonglong2*>(
                g_wd1t + (ic * 9 + t) * 128 + grp * 32);
#pragma unroll
            for (int q = 0; q < 8; q++) {
                ulonglong2 wq = wp[q];
                a0[2 * q]     = f2fma(vp0, wq.x, a0[2 * q]);
                a0[2 * q + 1] = f2fma(vp0, wq.y, a0[2 * q + 1]);
                a1[2 * q]     = f2fma(vp1, wq.x, a1[2 * q]);
                a1[2 * q + 1] = f2fma(vp1, wq.y, a1[2 * q + 1]);
            }
        }
    }

    const int oy = ty0 + py, ox0 = tx0 + px, ox1 = tx0 + px + 8;
#pragma unroll
    for (int q = 0; q < 16; q++) {
        int oc = grp * 32 + 2 * q;
        float p0a, p0b, p1a, p1b;
        upk(a0[q], p0a, p0b); upk(a1[q], p1a, p1b);
        float r;
        r = p0a + bias[oc];     g_g1[((b * 128 + oc) * 64 + oy) * 64 + ox0]     = r > 0.f ? r : 0.f;
        r = p0b + bias[oc + 1]; g_g1[((b * 128 + oc + 1) * 64 + oy) * 64 + ox0] = r > 0.f ? r : 0.f;
        r = p1a + bias[oc];     g_g1[((b * 128 + oc) * 64 + oy) * 64 + ox1]     = r > 0.f ? r : 0.f;
        r = p1b + bias[oc + 1]; g_g1[((b * 128 + oc + 1) * 64 + oy) * 64 + ox1] = r > 0.f ? r : 0.f;
    }
}

// ---------------------------------------------------------------------------
// d2: convT 128->64 k4 s2 p1, 64->128, relu.  fp32 packed; NCHW out.
// ---------------------------------------------------------------------------
__global__ void d2_kernel(const float* __restrict__ bias) {
    __shared__ float in_s[128 * 60];
    const int s = blockIdx.x, b = blockIdx.z;
    const int tid = threadIdx.x;
    const int pos = tid & 63, grp = tid >> 6;
    const int py = pos >> 3, px = pos & 7;
    const int ty0 = (s >> 3) * 8, tx0 = (s & 7) * 16;
    const int iby = (ty0 >> 1) - 1, ibx = (tx0 >> 1) - 1;

    for (int idx = tid; idx < 7680; idx += 128) {
        int ic = idx / 60, r = idx % 60;
        int iy = r / 10, ix = r % 10;
        int gy = iby + iy, gx = ibx + ix;
        float v = 0.f;
        if ((unsigned)gy < 64u && (unsigned)gx < 64u)
            v = g_g1[((b * 128 + ic) * 64 + gy) * 64 + gx];
        in_s[idx] = v;
    }
    __syncthreads();

    const int oy = ty0 + py, ox0 = tx0 + px, ox1 = tx0 + px + 8;
    const int kya = (oy & 1) ? 0 : 1;
    const int kxa = (ox0 & 1) ? 0 : 1;
    const int r0 = ((oy + 1 - kya) >> 1) - iby;
    const int c0 = ((ox0 + 1 - kxa) >> 1) - ibx;

    u64 a0[16], a1[16];
#pragma unroll
    for (int q = 0; q < 16; q++) { a0[q] = 0ull; a1[q] = 0ull; }

#pragma unroll 2
    for (int ic = 0; ic < 128; ic++) {
#pragma unroll
        for (int a = 0; a < 2; a++) {
            int ky = kya + 2 * a, ry = r0 - a;
#pragma unroll
            for (int c = 0; c < 2; c++) {
                int kx = kxa + 2 * c;
                float v0 = in_s[ic * 60 + ry * 10 + c0 - c];
                float v1 = in_s[ic * 60 + ry * 10 + c0 + 4 - c];
                u64 vp0 = pk(v0, v0), vp1 = pk(v1, v1);
                const ulonglong2* wp = reinterpret_cast<const ulonglong2*>(
                    g_wd2t + (ic * 16 + ky * 4 + kx) * 64 + grp * 32);
#pragma unroll
                for (int q = 0; q < 8; q++) {
                    ulonglong2 wq = wp[q];
                    a0[2 * q]     = f2fma(vp0, wq.x, a0[2 * q]);
                    a0[2 * q + 1] = f2fma(vp0, wq.y, a0[2 * q + 1]);
                    a1[2 * q]     = f2fma(vp1, wq.x, a1[2 * q]);
                    a1[2 * q + 1] = f2fma(vp1, wq.y, a1[2 * q + 1]);
                }
            }
        }
    }

#pragma unroll
    for (int q = 0; q < 16; q++) {
        int oc = grp * 32 + 2 * q;
        float p0a, p0b, p1a, p1b;
        upk(a0[q], p0a, p0b); upk(a1[q], p1a, p1b);
        float r;
        r = p0a + bias[oc];     g_g2[((b * 64 + oc) * 128 + oy) * 128 + ox0]     = r > 0.f ? r : 0.f;
        r = p0b + bias[oc + 1]; g_g2[((b * 64 + oc + 1) * 128 + oy) * 128 + ox0] = r > 0.f ? r : 0.f;
        r = p1a + bias[oc];     g_g2[((b * 64 + oc) * 128 + oy) * 128 + ox1]     = r > 0.f ? r : 0.f;
        r = p1b + bias[oc + 1]; g_g2[((b * 64 + oc + 1) * 128 + oy) * 128 + ox1] = r > 0.f ? r : 0.f;
    }
}

// ---------------------------------------------------------------------------
// d3: convT 64->3 k4 s2 p1, 128->256, no relu.
// ---------------------------------------------------------------------------
__global__ void d3_kernel(const float* __restrict__ bias, const float* __restrict__ w,
                          float* __restrict__ out) {
    __shared__ float w_s[3072];
    const int tid = threadIdx.x;
    for (int i = tid; i < 3072; i += 256) w_s[i] = w[i];
    __syncthreads();

    int gid = blockIdx.x * 256 + tid;
    int b = gid >> 16;
    int p = gid & 65535;
    int oy = p >> 8, ox = p & 255;
    const int kya = (oy & 1) ? 0 : 1;
    const int kxa = (ox & 1) ? 0 : 1;

    float acc0 = 0.f, acc1 = 0.f, acc2 = 0.f;
#pragma unroll
    for (int a = 0; a < 2; a++) {
        int ky = kya + 2 * a;
        int iy = (oy + 1 - ky) >> 1;
        if ((unsigned)iy >= 128u) continue;
#pragma unroll
        for (int c = 0; c < 2; c++) {
            int kx = kxa + 2 * c;
            int ix = (ox + 1 - kx) >> 1;
            if ((unsigned)ix >= 128u) continue;
            int t = ky * 4 + kx;
            const float* ip = g_g2 + ((b * 64) * 128 + iy) * 128 + ix;
#pragma unroll 8
            for (int ic = 0; ic < 64; ic++) {
                float v = ip[ic * 16384];
                acc0 += v * w_s[(ic * 3 + 0) * 16 + t];
                acc1 += v * w_s[(ic * 3 + 1) * 16 + t];
                acc2 += v * w_s[(ic * 3 + 2) * 16 + t];
            }
        }
    }
    int ob = b * 3 * 65536 + oy * 256 + ox;
    out[ob]             = acc0 + bias[0];
    out[ob + 65536]     = acc1 + bias[1];
    out[ob + 2 * 65536] = acc2 + bias[2];
}

// ---------------------------------------------------------------------------
extern "C" void kernel_launch(void* const* d_in, const int* in_sizes, int n_in,
                              void* d_out, int out_size) {
    const float* x     = (const float*)d_in[0];
    const float* e_w1  = (const float*)d_in[1];
    const float* e_b1  = (const float*)d_in[2];
    const float* e_w2  = (const float*)d_in[3];
    const float* e_b2  = (const float*)d_in[4];
    const float* e_w3  = (const float*)d_in[5];
    const float* e_b3  = (const float*)d_in[6];
    const float* embed = (const float*)d_in[7];
    const float* d_w1  = (const float*)d_in[8];
    const float* d_b1  = (const float*)d_in[9];
    const float* d_w2  = (const float*)d_in[10];
    const float* d_b2  = (const float*)d_in[11];
    const float* d_w3  = (const float*)d_in[12];
    const float* d_b3  = (const float*)d_in[13];
    float* out = (float*)d_out;

    prep_weights<<<512, 256>>>(e_w2, e_w3, d_w1, d_w2);
    e1_kernel<<<dim3(128, 2, BATCH), 128>>>(x, e_w1, e_b1);
    e2_kernel<<<dim3(32, 2, BATCH), 256>>>(e_b2);
    e3_kernel<<<dim3(64, 1, BATCH), 256>>>(e_b3);
    vq_kernel<<<1024, 128>>>(embed);
    loss_reduce_kernel<<<1, 256>>>(out, out_size - 1);
    d1_kernel<<<dim3(32, 1, BATCH), 256>>>(d_b1);
    d2_kernel<<<dim3(128, 1, BATCH), 128>>>(d_b2);
    d3_kernel<<<8192, 256>>>(d_b3, d_w3, out);
}

// round 15
// speedup vs baseline: 1.0442x; 1.0442x over previous
#include <cuda_runtime.h>

// ---------------------------------------------------------------------------
// VQ-VAE forward.  Encoder in double-float (df48) on the fp32 pipe (f32x2) --
// z must round to the exact value (any argmin flip fails).  VQ emulates the
// reference's fp32 distance rounding.  Decoder fp32 packed (NCHW g2).
// R11 configuration (best measured).
// ---------------------------------------------------------------------------

#define BATCH 32
typedef unsigned long long u64;

__device__ float2 g_h1[BATCH * 64 * 128 * 128];   // e1 out NCHW, df(hi,lo)
__device__ float2 g_h2[BATCH * 128 * 64 * 64];    // e2 out NCHW, df(hi,lo)
__device__ float  g_z32[BATCH * 64 * 64 * 32];    // e3 out BHWC, fp32
__device__ float  g_zq[BATCH * 64 * 64 * 32];     // straight-through z_q_st
__device__ float  g_g1[BATCH * 128 * 64 * 64];    // d1 out NCHW
__device__ float  g_g2[BATCH * 64 * 128 * 128];   // d2 out NCHW
__device__ double g_lp[1024];                     // loss partials

// transposed weights, [ic][tap][oc] (oc contiguous -> adjacent pairs = u64)
__device__ __align__(16) float g_we2t[64 * 16 * 128];
__device__ __align__(16) float g_we3t[128 * 9 * 32];
__device__ __align__(16) float g_wd1t[32 * 9 * 128];   // tap pre-flipped
__device__ __align__(16) float g_wd2t[128 * 16 * 64];

// ---- packed f32x2 helpers --------------------------------------------------
__device__ __forceinline__ u64 pk(float a, float b) {
    u64 r; asm("mov.b64 %0,{%1,%2};" : "=l"(r) : "f"(a), "f"(b)); return r;
}
__device__ __forceinline__ void upk(u64 v, float& a, float& b) {
    asm("mov.b64 {%0,%1},%2;" : "=f"(a), "=f"(b) : "l"(v));
}
__device__ __forceinline__ u64 f2mul(u64 a, u64 b) {
    u64 d; asm("mul.rn.f32x2 %0,%1,%2;" : "=l"(d) : "l"(a), "l"(b)); return d;
}
__device__ __forceinline__ u64 f2add(u64 a, u64 b) {
    u64 d; asm("add.rn.f32x2 %0,%1,%2;" : "=l"(d) : "l"(a), "l"(b)); return d;
}
__device__ __forceinline__ u64 f2fma(u64 a, u64 b, u64 c) {
    u64 d; asm("fma.rn.f32x2 %0,%1,%2,%3;" : "=l"(d) : "l"(a), "l"(b), "l"(c)); return d;
}

// ---- cp.async helpers ------------------------------------------------------
__device__ __forceinline__ unsigned smem_u32(const void* p) {
    unsigned a;
    asm("{ .reg .u64 t; cvta.to.shared.u64 t, %1; cvt.u32.u64 %0, t; }"
        : "=r"(a) : "l"(p));
    return a;
}
__device__ __forceinline__ void cp_async8(unsigned dst, const void* src, bool ok) {
    int sz = ok ? 8 : 0;
    asm volatile("cp.async.ca.shared.global [%0], [%1], 8, %2;"
                 :: "r"(dst), "l"(src), "r"(sz));
}
__device__ __forceinline__ void cp_commit() {
    asm volatile("cp.async.commit_group;");
}
template<int N> __device__ __forceinline__ void cp_wait() {
    asm volatile("cp.async.wait_group %0;" :: "n"(N));
}

// df MAC, fp32 scalar input (exact), packed weight pair: 7 packed ops
#define DFMAC_F(hi, lo, vd, vdn, w2)                               \
    {   u64 _p  = f2mul(vd, w2);                                   \
        u64 _nc = f2fma(vdn, w2, _p);                              \
        u64 _s  = f2add(hi, _p);                                   \
        u64 _t  = f2fma(hi, NEG1, _s);                             \
        u64 _nr = f2fma(_p, NEG1, _t);                             \
        u64 _nd = f2add(_nr, _nc);                                 \
        lo = f2fma(_nd, NEG1, lo);                                 \
        hi = _s; }

// df MAC, df input: 8 packed ops
#define DFMAC_DF(hi, lo, vd, vdn, vln, w2)                         \
    {   u64 _p  = f2mul(vd, w2);                                   \
        u64 _nc = f2fma(vdn, w2, _p);                              \
        _nc = f2fma(vln, w2, _nc);                                 \
        u64 _s  = f2add(hi, _p);                                   \
        u64 _t  = f2fma(hi, NEG1, _s);                             \
        u64 _nr = f2fma(_p, NEG1, _t);                             \
        u64 _nd = f2add(_nr, _nc);                                 \
        lo = f2fma(_nd, NEG1, lo);                                 \
        hi = _s; }

__device__ __forceinline__ float2 df_relu_out(u64 hiP, u64 loP, bool high,
                                              float bias) {
    float ah, bh, al, bl;
    upk(hiP, ah, bh); upk(loP, al, bl);
    double dv = high ? ((double)bh + (double)bl + (double)bias)
                     : ((double)ah + (double)al + (double)bias);
    float2 o;
    if (dv > 0.0) { o.x = (float)dv; o.y = (float)(dv - (double)o.x); }
    else          { o.x = 0.f; o.y = 0.f; }
    return o;
}

// ---------------------------------------------------------------------------
// prep: transpose weights into [ic][tap][oc] device buffers.
// ---------------------------------------------------------------------------
__global__ void prep_weights(const float* __restrict__ e_w2,
                             const float* __restrict__ e_w3,
                             const float* __restrict__ d_w1,
                             const float* __restrict__ d_w2) {
    int i = blockIdx.x * 256 + threadIdx.x;
    if (i < 131072) {            // e2: [64ic][16t][128oc]
        int oc = i & 127, t = (i >> 7) & 15, ic = i >> 11;
        g_we2t[i] = e_w2[(oc * 64 + ic) * 16 + t];
    }
    if (i < 36864) {             // e3: [128ic][9t][32oc]
        int oc = i & 31, j = i >> 5, t = j % 9, ic = j / 9;
        g_we3t[i] = e_w3[(oc * 128 + ic) * 9 + t];
    }
    if (i < 36864) {             // d1: [32ic][9t][128oc], tap flipped
        int oc = i & 127, j = i >> 7, t = j % 9, ic = j / 9;
        g_wd1t[i] = d_w1[(ic * 128 + oc) * 9 + (8 - t)];
    }
    if (i < 131072) {            // d2: [128ic][16t][64oc]
        int oc = i & 63, j = i >> 6, t = j & 15, ic = j >> 4;
        g_wd2t[i] = d_w2[(ic * 64 + oc) * 16 + t];
    }
}

// ---------------------------------------------------------------------------
// e1: conv 3->64, k4 s2 p1, 256->128, relu.  df out.  smem-staged input.
// ---------------------------------------------------------------------------
__global__ void e1_kernel(const float* __restrict__ x, const float* __restrict__ w,
                          const float* __restrict__ bias) {
    __shared__ __align__(8) float w_s[48 * 32];
    __shared__ float in_s[3][4][260];                 // [ic][ky][ix+1]
    const int oy = blockIdx.x, half = blockIdx.y, b = blockIdx.z;
    const int ox = threadIdx.x;
    for (int i = threadIdx.x; i < 1536; i += 128) {
        int t = i >> 5, j = i & 31;
        w_s[t * 32 + j] = w[(half * 32 + j) * 48 + t];
    }
    for (int idx = threadIdx.x; idx < 3096; idx += 128) {
        int ic = idx / 1032, r = idx % 1032;
        int ky = r / 258, ixm = r % 258;
        int iy = 2 * oy - 1 + ky, gx = ixm - 1;
        float v = 0.f;
        if ((unsigned)iy < 256u && (unsigned)gx < 256u)
            v = x[((b * 3 + ic) * 256 + iy) * 256 + gx];
        in_s[ic][ky][ixm] = v;
    }
    __syncthreads();
    const u64* w64 = reinterpret_cast<const u64*>(w_s);
    const u64 NEG1 = pk(-1.f, -1.f);

    u64 ahi[16], alo[16];
#pragma unroll
    for (int q = 0; q < 16; q++) { ahi[q] = 0ull; alo[q] = 0ull; }

#pragma unroll
    for (int ic = 0; ic < 3; ic++) {
#pragma unroll
        for (int ky = 0; ky < 4; ky++) {
#pragma unroll
            for (int kx = 0; kx < 4; kx++) {
                float v = in_s[ic][ky][2 * ox + kx];
                u64 vd = pk(v, v), vdn = pk(-v, -v);
                const u64* wp = w64 + (ic * 16 + ky * 4 + kx) * 16;
#pragma unroll
                for (int q = 0; q < 16; q++)
                    DFMAC_F(ahi[q], alo[q], vd, vdn, wp[q]);
            }
        }
    }
#pragma unroll
    for (int q = 0; q < 16; q++) {
        int oc = half * 32 + 2 * q;
        g_h1[((b * 64 + oc) * 128 + oy) * 128 + ox] =
            df_relu_out(ahi[q], alo[q], false, bias[oc]);
        g_h1[((b * 64 + oc + 1) * 128 + oy) * 128 + ox] =
            df_relu_out(ahi[q], alo[q], true, bias[oc + 1]);
    }
}

// ---------------------------------------------------------------------------
// e2: conv 64->128, k4 s2 p1, 128->64, relu.  df.  2 pixels/thread.
// 256 threads, ocT in {0,1}, 4-ic double-buffered cp.async stages.
// ---------------------------------------------------------------------------
__global__ void __launch_bounds__(256, 2)
e2_kernel(const float* __restrict__ bias) {
    __shared__ float2 in_s[2][4 * 18 * 34];
    const int s = blockIdx.x, ocT = blockIdx.y, b = blockIdx.z;
    const int tid = threadIdx.x;
    const int pos = tid & 63, grp = tid >> 6;
    const int py = pos >> 3, px = pos & 7;
    const int ty0 = (s >> 2) * 8, tx0 = (s & 3) * 16;
    const int iyb = 2 * ty0 - 1, ixb = 2 * tx0 - 1;
    const int ocbase = ocT * 64 + grp * 16;
    const u64 NEG1 = pk(-1.f, -1.f);
    const unsigned sb0 = smem_u32(&in_s[0][0]);

    u64 a0[8], l0[8], a1[8], l1[8];
#pragma unroll
    for (int q = 0; q < 8; q++) { a0[q] = 0ull; l0[q] = 0ull; a1[q] = 0ull; l1[q] = 0ull; }

    auto load_stage = [&](int icc, int buf) {
        unsigned base = sb0 + (unsigned)buf * 2448u * 8u;
        for (int idx = tid; idx < 2448; idx += 256) {
            int ic = idx / 612, r = idx % 612;
            int iy = r / 34, ix = r % 34;
            int gy = iyb + iy, gx = ixb + ix;
            bool ok = ((unsigned)gy < 128u && (unsigned)gx < 128u);
            const float2* src = &g_h1[((b * 64 + icc * 4 + ic) * 128 +
                                       (ok ? gy : 0)) * 128 + (ok ? gx : 0)];
            cp_async8(base + (unsigned)idx * 8u, src, ok);
        }
        cp_commit();
    };

    load_stage(0, 0);

    for (int icc = 0; icc < 16; icc++) {
        if (icc < 15) { load_stage(icc + 1, (icc + 1) & 1); cp_wait<1>(); }
        else          { cp_wait<0>(); }
        __syncthreads();

        const float2* cur = in_s[icc & 1];
#pragma unroll
        for (int ic = 0; ic < 4; ic++) {
#pragma unroll
            for (int ky = 0; ky < 4; ky++) {
                const float2* row = cur + ic * 612 + (2 * py + ky) * 34 + 2 * px;
#pragma unroll
                for (int kx = 0; kx < 4; kx++) {
                    float2 v0 = row[kx];
                    float2 v1 = row[kx + 16];
                    const ulonglong2* wp = reinterpret_cast<const ulonglong2*>(
                        g_we2t + ((icc * 4 + ic) * 16 + ky * 4 + kx) * 128 + ocbase);
                    ulonglong2 wq0 = wp[0], wq1 = wp[1], wq2 = wp[2], wq3 = wp[3];
                    u64 w2[8];
                    w2[0] = wq0.x; w2[1] = wq0.y;
                    w2[2] = wq1.x; w2[3] = wq1.y;
                    w2[4] = wq2.x; w2[5] = wq2.y;
                    w2[6] = wq3.x; w2[7] = wq3.y;
                    u64 vd0 = pk(v0.x, v0.x), vdn0 = pk(-v0.x, -v0.x), vln0 = pk(-v0.y, -v0.y);
                    u64 vd1 = pk(v1.x, v1.x), vdn1 = pk(-v1.x, -v1.x), vln1 = pk(-v1.y, -v1.y);
#pragma unroll
                    for (int q = 0; q < 8; q++) {
                        DFMAC_DF(a0[q], l0[q], vd0, vdn0, vln0, w2[q]);
                        DFMAC_DF(a1[q], l1[q], vd1, vdn1, vln1, w2[q]);
                    }
                }
            }
        }
        __syncthreads();
    }

    const int oy = ty0 + py, ox0 = tx0 + px, ox1 = tx0 + px + 8;
#pragma unroll
    for (int q = 0; q < 8; q++) {
        int oc = ocbase + 2 * q;
        long b0 = ((long)(b * 128 + oc) * 64 + oy) * 64;
        long b1 = ((long)(b * 128 + oc + 1) * 64 + oy) * 64;
        g_h2[b0 + ox0] = df_relu_out(a0[q], l0[q], false, bias[oc]);
        g_h2[b1 + ox0] = df_relu_out(a0[q], l0[q], true,  bias[oc + 1]);
        g_h2[b0 + ox1] = df_relu_out(a1[q], l1[q], false, bias[oc]);
        g_h2[b1 + ox1] = df_relu_out(a1[q], l1[q], true,  bias[oc + 1]);
    }
}

// ---------------------------------------------------------------------------
// e3: conv 128->32, k3 s1 p1, 64->64, relu.  df in, fp32 out BHWC.
// ---------------------------------------------------------------------------
__global__ void e3_kernel(const float* __restrict__ bias) {
    __shared__ float2 in_s[2][8 * 100];
    const int s = blockIdx.x, b = blockIdx.z;
    const int tid = threadIdx.x;
    const int pos = tid & 63, grp = tid >> 6;
    const int py = pos >> 3, px = pos & 7;
    const int ty0 = (s >> 3) * 8, tx0 = (s & 7) * 8;
    const u64 NEG1 = pk(-1.f, -1.f);
    const unsigned sb0 = smem_u32(&in_s[0][0]);

    u64 ahi[4], alo[4];
#pragma unroll
    for (int q = 0; q < 4; q++) { ahi[q] = 0ull; alo[q] = 0ull; }

    auto load_stage = [&](int icc, int buf) {
        unsigned base = sb0 + (unsigned)buf * 800u * 8u;
        for (int idx = tid; idx < 800; idx += 256) {
            int ic = idx / 100, r = idx % 100;
            int iy = r / 10, ix = r % 10;
            int gy = ty0 - 1 + iy, gx = tx0 - 1 + ix;
            bool ok = ((unsigned)gy < 64u && (unsigned)gx < 64u);
            const float2* src = &g_h2[((b * 128 + icc * 8 + ic) * 64 +
                                       (ok ? gy : 0)) * 64 + (ok ? gx : 0)];
            cp_async8(base + (unsigned)idx * 8u, src, ok);
        }
        cp_commit();
    };

    load_stage(0, 0);

    for (int icc = 0; icc < 16; icc++) {
        if (icc < 15) { load_stage(icc + 1, (icc + 1) & 1); cp_wait<1>(); }
        else          { cp_wait<0>(); }
        __syncthreads();

        const float2* cur = in_s[icc & 1];
#pragma unroll
        for (int ic = 0; ic < 8; ic++) {
#pragma unroll
            for (int t = 0; t < 9; t++) {
                int ky = t / 3, kx = t % 3;
                float2 v = cur[ic * 100 + (py + ky) * 10 + px + kx];
                u64 vd  = pk(v.x, v.x);
                u64 vdn = pk(-v.x, -v.x);
                u64 vln = pk(-v.y, -v.y);
                const ulonglong2* wp = reinterpret_cast<const ulonglong2*>(
                    g_we3t + ((icc * 8 + ic) * 9 + t) * 32 + grp * 8);
                ulonglong2 wqa = wp[0], wqb = wp[1];
                DFMAC_DF(ahi[0], alo[0], vd, vdn, vln, wqa.x);
                DFMAC_DF(ahi[1], alo[1], vd, vdn, vln, wqa.y);
                DFMAC_DF(ahi[2], alo[2], vd, vdn, vln, wqb.x);
                DFMAC_DF(ahi[3], alo[3], vd, vdn, vln, wqb.y);
            }
        }
        __syncthreads();
    }

    const int oy = ty0 + py, ox = tx0 + px;
    int base = ((b * 64 + oy) * 64 + ox) * 32 + grp * 8;
#pragma unroll
    for (int q = 0; q < 4; q++) {
        float ah, bh, al, bl;
        upk(ahi[q], ah, bh); upk(alo[q], al, bl);
        double d0 = (double)ah + (double)al + (double)bias[grp * 8 + 2 * q];
        double d1 = (double)bh + (double)bl + (double)bias[grp * 8 + 2 * q + 1];
        float z0 = (float)d0, z1 = (float)d1;
        g_z32[base + 2 * q]     = z0 > 0.f ? z0 : 0.f;
        g_z32[base + 2 * q + 1] = z1 > 0.f ? z1 : 0.f;
    }
}

// ---------------------------------------------------------------------------
// VQ, reference-fp32-emulating (tie-exact).
// ---------------------------------------------------------------------------
__global__ void vq_kernel(const float* __restrict__ embed) {
    __shared__ float s_e[128 * 33];
    __shared__ float s_B[128];
    __shared__ double s_red[128];
    const int tid = threadIdx.x;
    const long n = (long)blockIdx.x * 128 + tid;

    float zv[32];
    {
        const float4* zp = reinterpret_cast<const float4*>(g_z32 + n * 32);
#pragma unroll
        for (int d = 0; d < 8; d++) {
            float4 t = zp[d];
            zv[4 * d] = t.x; zv[4 * d + 1] = t.y;
            zv[4 * d + 2] = t.z; zv[4 * d + 3] = t.w;
        }
    }

    float A = 0.f;
#pragma unroll
    for (int d = 0; d < 32; d++)
        A = __fadd_rn(A, __fmul_rn(zv[d], zv[d]));

    float best = 3.402823466e38f;
    int bidx = 0;

    for (int c = 0; c < 4; c++) {
        __syncthreads();
        {
            const float* ep = embed + (c * 128 + tid) * 32;
            float Bacc = 0.f;
#pragma unroll
            for (int d = 0; d < 32; d++) {
                float e = ep[d];
                s_e[tid * 33 + d] = e;
                Bacc = __fadd_rn(Bacc, __fmul_rn(e, e));
            }
            s_B[tid] = Bacc;
        }
        __syncthreads();

        for (int e = 0; e < 128; e++) {
            float m = 0.f;
#pragma unroll
            for (int d = 0; d < 32; d++)
                m = __fmaf_rn(zv[d], s_e[e * 33 + d], m);
            float t1 = __fadd_rn(A, s_B[e]);
            float sc = __fsub_rn(t1, __fmul_rn(2.f, m));
            if (sc < best) { best = sc; bidx = c * 128 + e; }
        }
    }

    const float* eb = embed + bidx * 32;
    float st[32];
    double ls = 0.0;
#pragma unroll
    for (int d = 0; d < 32; d++) {
        float q = eb[d];
        float diff = __fsub_rn(q, zv[d]);
        st[d] = __fadd_rn(zv[d], diff);
        ls += (double)diff * (double)diff;
    }
    float4* qout = reinterpret_cast<float4*>(g_zq + n * 32);
#pragma unroll
    for (int q = 0; q < 8; q++)
        qout[q] = make_float4(st[4 * q], st[4 * q + 1], st[4 * q + 2], st[4 * q + 3]);

    s_red[tid] = ls;
    __syncthreads();
    for (int off = 64; off > 0; off >>= 1) {
        if (tid < off) s_red[tid] += s_red[tid + off];
        __syncthreads();
    }
    if (tid == 0) g_lp[blockIdx.x] = s_red[0];
}

__global__ void loss_reduce_kernel(float* __restrict__ out, int lossIdx) {
    __shared__ double s[256];
    int tid = threadIdx.x;
    s[tid] = g_lp[tid] + g_lp[tid + 256] + g_lp[tid + 512] + g_lp[tid + 768];
    __syncthreads();
    for (int off = 128; off > 0; off >>= 1) {
        if (tid < off) s[tid] += s[tid + off];
        __syncthreads();
    }
    if (tid == 0) out[lossIdx] = (float)(1.25 * s[0] / 4194304.0);
}

// ---------------------------------------------------------------------------
// d1: convT 32->128 k3 s1 p1.  fp32 packed; ulonglong2 weight loads.
// ---------------------------------------------------------------------------
__global__ void d1_kernel(const float* __restrict__ bias) {
    __shared__ float in_s[32 * 180];
    const int s = blockIdx.x, b = blockIdx.z;
    const int tid = threadIdx.x;
    const int pos = tid & 63, grp = tid >> 6;
    const int py = pos >> 3, px = pos & 7;
    const int ty0 = (s >> 2) * 8, tx0 = (s & 3) * 16;

    for (int i = tid; i < 1440; i += 256) {
        int pix = i >> 3, c4 = i & 7;
        int iy = pix / 18, ix = pix % 18;
        int gy = ty0 - 1 + iy, gx = tx0 - 1 + ix;
        float4 v = make_float4(0.f, 0.f, 0.f, 0.f);
        if ((unsigned)gy < 64u && (unsigned)gx < 64u)
            v = *reinterpret_cast<const float4*>(
                g_zq + ((b * 64 + gy) * 64 + gx) * 32 + c4 * 4);
        in_s[(c4 * 4 + 0) * 180 + pix] = v.x;
        in_s[(c4 * 4 + 1) * 180 + pix] = v.y;
        in_s[(c4 * 4 + 2) * 180 + pix] = v.z;
        in_s[(c4 * 4 + 3) * 180 + pix] = v.w;
    }
    __syncthreads();

    u64 a0[16], a1[16];
#pragma unroll
    for (int q = 0; q < 16; q++) { a0[q] = 0ull; a1[q] = 0ull; }

#pragma unroll 2
    for (int ic = 0; ic < 32; ic++) {
#pragma unroll
        for (int t = 0; t < 9; t++) {
            int ky = t / 3, kx = t % 3;
            float v0 = in_s[ic * 180 + (py + ky) * 18 + px + kx];
            float v1 = in_s[ic * 180 + (py + ky) * 18 + px + 8 + kx];
            u64 vp0 = pk(v0, v0), vp1 = pk(v1, v1);
            const ulonglong2* wp = reinterpret_cast<const ulonglong2*>(
                g_wd1t + (ic * 9 + t) * 128 + grp * 32);
#pragma unroll
            for (int q = 0; q < 8; q++) {
                ulonglong2 wq = wp[q];
                a0[2 * q]     = f2fma(vp0, wq.x, a0[2 * q]);
                a0[2 * q + 1] = f2fma(vp0, wq.y, a0[2 * q + 1]);
                a1[2 * q]     = f2fma(vp1, wq.x, a1[2 * q]);
                a1[2 * q + 1] = f2fma(vp1, wq.y, a1[2 * q + 1]);
            }
        }
    }

    const int oy = ty0 + py, ox0 = tx0 + px, ox1 = tx0 + px + 8;
#pragma unroll
    for (int q = 0; q < 16; q++) {
        int oc = grp * 32 + 2 * q;
        float p0a, p0b, p1a, p1b;
        upk(a0[q], p0a, p0b); upk(a1[q], p1a, p1b);
        float r;
        r = p0a + bias[oc];     g_g1[((b * 128 + oc) * 64 + oy) * 64 + ox0]     = r > 0.f ? r : 0.f;
        r = p0b + bias[oc + 1]; g_g1[((b * 128 + oc + 1) * 64 + oy) * 64 + ox0] = r > 0.f ? r : 0.f;
        r = p1a + bias[oc];     g_g1[((b * 128 + oc) * 64 + oy) * 64 + ox1]     = r > 0.f ? r : 0.f;
        r = p1b + bias[oc + 1]; g_g1[((b * 128 + oc + 1) * 64 + oy) * 64 + ox1] = r > 0.f ? r : 0.f;
    }
}

// ---------------------------------------------------------------------------
// d2: convT 128->64 k4 s2 p1, 64->128, relu.  fp32 packed; NCHW out.
// ---------------------------------------------------------------------------
__global__ void d2_kernel(const float* __restrict__ bias) {
    __shared__ float in_s[128 * 60];
    const int s = blockIdx.x, b = blockIdx.z;
    const int tid = threadIdx.x;
    const int pos = tid & 63, grp = tid >> 6;
    const int py = pos >> 3, px = pos & 7;
    const int ty0 = (s >> 3) * 8, tx0 = (s & 7) * 16;
    const int iby = (ty0 >> 1) - 1, ibx = (tx0 >> 1) - 1;

    for (int idx = tid; idx < 7680; idx += 128) {
        int ic = idx / 60, r = idx % 60;
        int iy = r / 10, ix = r % 10;
        int gy = iby + iy, gx = ibx + ix;
        float v = 0.f;
        if ((unsigned)gy < 64u && (unsigned)gx < 64u)
            v = g_g1[((b * 128 + ic) * 64 + gy) * 64 + gx];
        in_s[idx] = v;
    }
    __syncthreads();

    const int oy = ty0 + py, ox0 = tx0 + px, ox1 = tx0 + px + 8;
    const int kya = (oy & 1) ? 0 : 1;
    const int kxa = (ox0 & 1) ? 0 : 1;
    const int r0 = ((oy + 1 - kya) >> 1) - iby;
    const int c0 = ((ox0 + 1 - kxa) >> 1) - ibx;

    u64 a0[16], a1[16];
#pragma unroll
    for (int q = 0; q < 16; q++) { a0[q] = 0ull; a1[q] = 0ull; }

#pragma unroll 2
    for (int ic = 0; ic < 128; ic++) {
#pragma unroll
        for (int a = 0; a < 2; a++) {
            int ky = kya + 2 * a, ry = r0 - a;
#pragma unroll
            for (int c = 0; c < 2; c++) {
                int kx = kxa + 2 * c;
                float v0 = in_s[ic * 60 + ry * 10 + c0 - c];
                float v1 = in_s[ic * 60 + ry * 10 + c0 + 4 - c];
                u64 vp0 = pk(v0, v0), vp1 = pk(v1, v1);
                const ulonglong2* wp = reinterpret_cast<const ulonglong2*>(
                    g_wd2t + (ic * 16 + ky * 4 + kx) * 64 + grp * 32);
#pragma unroll
                for (int q = 0; q < 8; q++) {
                    ulonglong2 wq = wp[q];
                    a0[2 * q]     = f2fma(vp0, wq.x, a0[2 * q]);
                    a0[2 * q + 1] = f2fma(vp0, wq.y, a0[2 * q + 1]);
                    a1[2 * q]     = f2fma(vp1, wq.x, a1[2 * q]);
                    a1[2 * q + 1] = f2fma(vp1, wq.y, a1[2 * q + 1]);
                }
            }
        }
    }

#pragma unroll
    for (int q = 0; q < 16; q++) {
        int oc = grp * 32 + 2 * q;
        float p0a, p0b, p1a, p1b;
        upk(a0[q], p0a, p0b); upk(a1[q], p1a, p1b);
        float r;
        r = p0a + bias[oc];     g_g2[((b * 64 + oc) * 128 + oy) * 128 + ox0]     = r > 0.f ? r : 0.f;
        r = p0b + bias[oc + 1]; g_g2[((b * 64 + oc + 1) * 128 + oy) * 128 + ox0] = r > 0.f ? r : 0.f;
        r = p1a + bias[oc];     g_g2[((b * 64 + oc) * 128 + oy) * 128 + ox1]     = r > 0.f ? r : 0.f;
        r = p1b + bias[oc + 1]; g_g2[((b * 64 + oc + 1) * 128 + oy) * 128 + ox1] = r > 0.f ? r : 0.f;
    }
}

// ---------------------------------------------------------------------------
// d3: convT 64->3 k4 s2 p1, 128->256, no relu.
// ---------------------------------------------------------------------------
__global__ void d3_kernel(const float* __restrict__ bias, const float* __restrict__ w,
                          float* __restrict__ out) {
    __shared__ float w_s[3072];
    const int tid = threadIdx.x;
    for (int i = tid; i < 3072; i += 256) w_s[i] = w[i];
    __syncthreads();

    int gid = blockIdx.x * 256 + tid;
    int b = gid >> 16;
    int p = gid & 65535;
    int oy = p >> 8, ox = p & 255;
    const int kya = (oy & 1) ? 0 : 1;
    const int kxa = (ox & 1) ? 0 : 1;

    float acc0 = 0.f, acc1 = 0.f, acc2 = 0.f;
#pragma unroll
    for (int a = 0; a < 2; a++) {
        int ky = kya + 2 * a;
        int iy = (oy + 1 - ky) >> 1;
        if ((unsigned)iy >= 128u) continue;
#pragma unroll
        for (int c = 0; c < 2; c++) {
            int kx = kxa + 2 * c;
            int ix = (ox + 1 - kx) >> 1;
            if ((unsigned)ix >= 128u) continue;
            int t = ky * 4 + kx;
            const float* ip = g_g2 + ((b * 64) * 128 + iy) * 128 + ix;
#pragma unroll 8
            for (int ic = 0; ic < 64; ic++) {
                float v = ip[ic * 16384];
                acc0 += v * w_s[(ic * 3 + 0) * 16 + t];
                acc1 += v * w_s[(ic * 3 + 1) * 16 + t];
                acc2 += v * w_s[(ic * 3 + 2) * 16 + t];
            }
        }
    }
    int ob = b * 3 * 65536 + oy * 256 + ox;
    out[ob]             = acc0 + bias[0];
    out[ob + 65536]     = acc1 + bias[1];
    out[ob + 2 * 65536] = acc2 + bias[2];
}

// ---------------------------------------------------------------------------
extern "C" void kernel_launch(void* const* d_in, const int* in_sizes, int n_in,
                              void* d_out, int out_size) {
    const float* x     = (const float*)d_in[0];
    const float* e_w1  = (const float*)d_in[1];
    const float* e_b1  = (const float*)d_in[2];
    const float* e_w2  = (const float*)d_in[3];
    const float* e_b2  = (const float*)d_in[4];
    const float* e_w3  = (const float*)d_in[5];
    const float* e_b3  = (const float*)d_in[6];
    const float* embed = (const float*)d_in[7];
    const float* d_w1  = (const float*)d_in[8];
    const float* d_b1  = (const float*)d_in[9];
    const float* d_w2  = (const float*)d_in[10];
    const float* d_b2  = (const float*)d_in[11];
    const float* d_w3  = (const float*)d_in[12];
    const float* d_b3  = (const float*)d_in[13];
    float* out = (float*)d_out;

    prep_weights<<<512, 256>>>(e_w2, e_w3, d_w1, d_w2);
    e1_kernel<<<dim3(128, 2, BATCH), 128>>>(x, e_w1, e_b1);
    e2_kernel<<<dim3(32, 2, BATCH), 256>>>(e_b2);
    e3_kernel<<<dim3(64, 1, BATCH), 256>>>(e_b3);
    vq_kernel<<<1024, 128>>>(embed);
    loss_reduce_kernel<<<1, 256>>>(out, out_size - 1);
    d1_kernel<<<dim3(32, 1, BATCH), 256>>>(d_b1);
    d2_kernel<<<dim3(128, 1, BATCH), 128>>>(d_b2);
    d3_kernel<<<8192, 256>>>(d_b3, d_w3, out);
}